// round 4
// baseline (speedup 1.0000x reference)
#include <cuda_runtime.h>
#include <cstdint>

// TopK-magnitude masking, per row.
//   x: (ROWS, 8192) fp32. K = 819 (=round(0.1*8192)).
//   out[r,c] = x[r,c] if |x[r,c]| >= (819th largest |x| in row r) else 0.
//
// One CTA per row. 256 threads x 32 floats/thread held in registers.
// Exact K-th largest |x| via 4-pass MSB-first radix select on the
// bit pattern of |x| (monotone for non-negative floats).

#define ROWLEN 8192
#define TPB    256
#define VPT    8          // float4 per thread -> 32 floats/thread
#define KSEL   819u

__global__ __launch_bounds__(TPB, 4)
void topk_mask_kernel(const float* __restrict__ x, float* __restrict__ out) {
    __shared__ unsigned hist[256];
    __shared__ unsigned scan[256];
    __shared__ unsigned sh_digit;
    __shared__ unsigned sh_gt;

    const int t   = threadIdx.x;
    const size_t row_off = (size_t)blockIdx.x * ROWLEN;
    const float4* __restrict__ px = reinterpret_cast<const float4*>(x + row_off);
    float4* __restrict__       po = reinterpret_cast<float4*>(out + row_off);

    // ---- load row into registers (coalesced float4) ----
    float4 v[VPT];
#pragma unroll
    for (int i = 0; i < VPT; i++) v[i] = px[t + i * TPB];

    // ---- radix select: find bit pattern T of the K-th largest |x| ----
    unsigned prefix = 0u;
    unsigned k = KSEL;

#pragma unroll
    for (int pass = 0; pass < 4; pass++) {
        const int shift = 24 - pass * 8;
        // mask of the bits already fixed by earlier passes
        const unsigned um = (pass == 0) ? 0x00000000u
                          : (pass == 1) ? 0xFF000000u
                          : (pass == 2) ? 0xFFFF0000u
                          :               0xFFFFFF00u;

        hist[t] = 0u;
        __syncthreads();

        // histogram of the current digit among keys matching the prefix,
        // with warp-aggregated atomics (Gaussian data -> heavy digit ties)
#pragma unroll
        for (int i = 0; i < VPT; i++) {
            const float* fv = reinterpret_cast<const float*>(&v[i]);
#pragma unroll
            for (int c = 0; c < 4; c++) {
                unsigned key = __float_as_uint(fv[c]) & 0x7FFFFFFFu;
                bool part = ((key ^ prefix) & um) == 0u;
                unsigned dig = (key >> shift) & 255u;
                unsigned act = __ballot_sync(0xFFFFFFFFu, part);
                if (part) {
                    unsigned m = __match_any_sync(act, dig);
                    if ((t & 31) == (__ffs(m) - 1))
                        atomicAdd(&hist[dig], (unsigned)__popc(m));
                }
            }
        }
        __syncthreads();

        // inclusive suffix scan: scan[d] = sum_{e>=d} hist[e]
        scan[t] = hist[t];
        __syncthreads();
#pragma unroll
        for (int off = 1; off < 256; off <<= 1) {
            unsigned a = scan[t];
            unsigned b = (t + off < 256) ? scan[t + off] : 0u;
            __syncthreads();
            scan[t] = a + b;
            __syncthreads();
        }

        // exactly one digit d satisfies: count(>d) < k <= count(>=d)
        {
            unsigned incl = scan[t];
            unsigned gt   = incl - hist[t];
            if (incl >= k && gt < k) { sh_digit = (unsigned)t; sh_gt = gt; }
        }
        __syncthreads();
        prefix |= sh_digit << shift;
        k      -= sh_gt;
        __syncthreads();   // protect hist/scan before next pass reset
    }

    const unsigned T = prefix;   // bit pattern of the K-th largest |x|

    // ---- apply mask and store (coalesced float4) ----
#pragma unroll
    for (int i = 0; i < VPT; i++) {
        float4 o = v[i];
        float* fo = reinterpret_cast<float*>(&o);
#pragma unroll
        for (int c = 0; c < 4; c++) {
            unsigned key = __float_as_uint(fo[c]) & 0x7FFFFFFFu;
            if (key < T) fo[c] = 0.0f;
        }
        po[t + i * TPB] = o;
    }
}

extern "C" void kernel_launch(void* const* d_in, const int* in_sizes, int n_in,
                              void* d_out, int out_size) {
    const float* x = (const float*)d_in[0];
    float* out = (float*)d_out;
    const int rows = in_sizes[0] / ROWLEN;   // 4096
    topk_mask_kernel<<<rows, TPB>>>(x, out);
}

// round 5
// speedup vs baseline: 2.5078x; 2.5078x over previous
#include <cuda_runtime.h>
#include <cstdint>

// TopK-magnitude masking, per row.
//   x: (4096, 8192) fp32, K = 819.
//   out[r,c] = x[r,c] if |x[r,c]| >= (K-th largest |x| in row r) else 0.
//
// One CTA per row, 512 threads x 16 floats register-resident.
// Exact K-th largest |x| via 3-pass radix select (12+12+7 bits) on bits(|x|).
// Histograms: plain predicated shared atomics (spread-address ATOMS ~2cyc/lane).
// Suffix scans: shfl-based, 2 barriers per scan.

#define ROWLEN 8192
#define TPB    512
#define VPT    4            // float4 per thread -> 16 floats
#define KSEL   819u
#define NW     (TPB / 32)   // 16 warps

__global__ __launch_bounds__(TPB, 2)
void topk_mask_kernel(const float* __restrict__ x, float* __restrict__ out) {
    __shared__ unsigned hist[4096];
    __shared__ unsigned wsum[NW];
    __shared__ unsigned wtail[NW];
    __shared__ unsigned sh_digit;
    __shared__ unsigned sh_k;

    const int t    = threadIdx.x;
    const int lane = t & 31;
    const int wid  = t >> 5;
    const size_t row_off = (size_t)blockIdx.x * ROWLEN;
    const float4* __restrict__ px = reinterpret_cast<const float4*>(x + row_off);
    float4*       __restrict__ po = reinterpret_cast<float4*>(out + row_off);

    // ---- load row into registers (coalesced float4), overlap with hist zero ----
    float4 v[VPT];
#pragma unroll
    for (int i = 0; i < VPT; i++) v[i] = px[t + i * TPB];

    {
        uint4 z = make_uint4(0u, 0u, 0u, 0u);
        uint4* h4 = reinterpret_cast<uint4*>(hist);
        h4[t] = z;
        h4[t + TPB] = z;
    }
    __syncthreads();

    unsigned k = KSEL;
    unsigned d1, d2, d3;

    // =============== pass 1: digit = key >> 19  (12 bits, 4096 bins) ===============
#pragma unroll
    for (int i = 0; i < VPT; i++) {
        const float* fv = reinterpret_cast<const float*>(&v[i]);
#pragma unroll
        for (int c = 0; c < 4; c++) {
            unsigned key = __float_as_uint(fv[c]) & 0x7FFFFFFFu;
            atomicAdd(&hist[key >> 19], 1u);
        }
    }
    __syncthreads();

    // ---- 4096-bin suffix scan + digit select (8 bins/thread) ----
    {
        const int base = t * 8;
        unsigned loc[8];
        unsigned s = 0u;
#pragma unroll
        for (int j = 7; j >= 0; j--) { s += hist[base + j]; loc[j] = s; }
        unsigned p = s;                       // warp suffix scan of chunk totals
#pragma unroll
        for (int off = 1; off < 32; off <<= 1) {
            unsigned n = __shfl_down_sync(0xFFFFFFFFu, p, off);
            if (lane < 32 - off) p += n;
        }
        if (lane == 0) wsum[wid] = p;         // warp total
        __syncthreads();
        if (t < NW) {
            unsigned q = wsum[t];
            unsigned r = q;
#pragma unroll
            for (int off = 1; off < NW; off <<= 1) {
                unsigned n = __shfl_down_sync(0x0000FFFFu, r, off);
                if (t < NW - off) r += n;
            }
            wtail[t] = r - q;                 // sum of warp totals AFTER warp t
        }
        __syncthreads();
        unsigned beyond = (p - s) + wtail[wid];   // count of keys in digits > this chunk
#pragma unroll
        for (int j = 0; j < 8; j++) {
            unsigned incl = loc[j] + beyond;                       // count(>= digit)
            unsigned cnt  = loc[j] - ((j < 7) ? loc[j + 1] : 0u);  // hist[digit]
            unsigned gt   = incl - cnt;                            // count(> digit)
            if (incl >= k && gt < k) { sh_digit = (unsigned)(base + j); sh_k = k - gt; }
        }
        __syncthreads();
        d1 = sh_digit; k = sh_k;
    }

    // =============== pass 2: digit = (key >> 7) & 0xFFF, prefix d1 ===============
    {
        uint4 z = make_uint4(0u, 0u, 0u, 0u);
        uint4* h4 = reinterpret_cast<uint4*>(hist);
        h4[t] = z;
        h4[t + TPB] = z;
    }
    __syncthreads();
#pragma unroll
    for (int i = 0; i < VPT; i++) {
        const float* fv = reinterpret_cast<const float*>(&v[i]);
#pragma unroll
        for (int c = 0; c < 4; c++) {
            unsigned key = __float_as_uint(fv[c]) & 0x7FFFFFFFu;
            if ((key >> 19) == d1)
                atomicAdd(&hist[(key >> 7) & 0xFFFu], 1u);
        }
    }
    __syncthreads();
    {
        const int base = t * 8;
        unsigned loc[8];
        unsigned s = 0u;
#pragma unroll
        for (int j = 7; j >= 0; j--) { s += hist[base + j]; loc[j] = s; }
        unsigned p = s;
#pragma unroll
        for (int off = 1; off < 32; off <<= 1) {
            unsigned n = __shfl_down_sync(0xFFFFFFFFu, p, off);
            if (lane < 32 - off) p += n;
        }
        if (lane == 0) wsum[wid] = p;
        __syncthreads();
        if (t < NW) {
            unsigned q = wsum[t];
            unsigned r = q;
#pragma unroll
            for (int off = 1; off < NW; off <<= 1) {
                unsigned n = __shfl_down_sync(0x0000FFFFu, r, off);
                if (t < NW - off) r += n;
            }
            wtail[t] = r - q;
        }
        __syncthreads();
        unsigned beyond = (p - s) + wtail[wid];
#pragma unroll
        for (int j = 0; j < 8; j++) {
            unsigned incl = loc[j] + beyond;
            unsigned cnt  = loc[j] - ((j < 7) ? loc[j + 1] : 0u);
            unsigned gt   = incl - cnt;
            if (incl >= k && gt < k) { sh_digit = (unsigned)(base + j); sh_k = k - gt; }
        }
        __syncthreads();
        d2 = sh_digit; k = sh_k;
    }

    // =============== pass 3: digit = key & 0x7F, prefix (d1,d2), 128 bins ===============
    const unsigned pref24 = (d1 << 12) | d2;    // top 24 bits of key, i.e. key >> 7
    if (t < 128) hist[t] = 0u;
    __syncthreads();
#pragma unroll
    for (int i = 0; i < VPT; i++) {
        const float* fv = reinterpret_cast<const float*>(&v[i]);
#pragma unroll
        for (int c = 0; c < 4; c++) {
            unsigned key = __float_as_uint(fv[c]) & 0x7FFFFFFFu;
            if ((key >> 7) == pref24)
                atomicAdd(&hist[key & 0x7Fu], 1u);
        }
    }
    __syncthreads();
    if (wid == 0) {                              // warp 0 scans 128 bins, 4/lane
        const int base = lane * 4;
        unsigned loc[4];
        unsigned s = 0u;
#pragma unroll
        for (int j = 3; j >= 0; j--) { s += hist[base + j]; loc[j] = s; }
        unsigned p = s;
#pragma unroll
        for (int off = 1; off < 32; off <<= 1) {
            unsigned n = __shfl_down_sync(0xFFFFFFFFu, p, off);
            if (lane < 32 - off) p += n;
        }
        unsigned beyond = p - s;
#pragma unroll
        for (int j = 0; j < 4; j++) {
            unsigned incl = loc[j] + beyond;
            unsigned cnt  = loc[j] - ((j < 3) ? loc[j + 1] : 0u);
            unsigned gt   = incl - cnt;
            if (incl >= k && gt < k) sh_digit = (unsigned)(base + j);
        }
    }
    __syncthreads();
    d3 = sh_digit;

    const unsigned T = (d1 << 19) | (d2 << 7) | d3;  // bit pattern of K-th largest |x|

    // ---- apply mask and store (coalesced float4) ----
#pragma unroll
    for (int i = 0; i < VPT; i++) {
        float4 o = v[i];
        float* fo = reinterpret_cast<float*>(&o);
#pragma unroll
        for (int c = 0; c < 4; c++) {
            unsigned key = __float_as_uint(fo[c]) & 0x7FFFFFFFu;
            if (key < T) fo[c] = 0.0f;
        }
        po[t + i * TPB] = o;
    }
}

extern "C" void kernel_launch(void* const* d_in, const int* in_sizes, int n_in,
                              void* d_out, int out_size) {
    const float* x = (const float*)d_in[0];
    float* out = (float*)d_out;
    const int rows = in_sizes[0] / ROWLEN;   // 4096
    topk_mask_kernel<<<rows, TPB>>>(x, out);
}

// round 6
// speedup vs baseline: 3.1076x; 1.2392x over previous
#include <cuda_runtime.h>
#include <cstdint>

// TopK-magnitude masking per row. x: (4096, 8192) fp32, K = 819.
// out[r,c] = x[r,c] if |x[r,c]| >= (K-th largest |x| in row r) else 0.
//
// One CTA per row, 512 threads. Row staged in SMEM (not registers) so the
// kernel fits 32 regs -> 4 CTAs/SM. Exact K-th largest |x| via 3-pass radix
// select (11+11+9 bits) on bits(|x|) with a 2048-bin shared histogram and
// shfl-based suffix scans (2 barriers per scan).

#define ROWLEN 8192
#define TPB    512
#define VPT    4            // float4 per thread -> 16 floats
#define KSEL   819u
#define NW     (TPB / 32)   // 16 warps

// Suffix-scan + digit select over hist[NBINS]; leaves result in *sh_digit /
// *sh_k. Ends with a __syncthreads so callers can read the results directly.
template <int NBINS>
__device__ __forceinline__ void suffix_select(
    const unsigned* __restrict__ hist, unsigned k,
    int t, int lane, int wid,
    unsigned* wsum, unsigned* wtail,
    unsigned* sh_digit, unsigned* sh_k)
{
    constexpr int B = NBINS / TPB;        // bins per thread (4 or 1)
    const int base = t * B;
    unsigned loc[B];
    unsigned s = 0u;
#pragma unroll
    for (int j = B - 1; j >= 0; j--) { s += hist[base + j]; loc[j] = s; }

    unsigned p = s;                        // warp suffix scan of chunk totals
#pragma unroll
    for (int off = 1; off < 32; off <<= 1) {
        unsigned n = __shfl_down_sync(0xFFFFFFFFu, p, off);
        if (lane < 32 - off) p += n;
    }
    if (lane == 0) wsum[wid] = p;
    __syncthreads();
    if (t < NW) {
        unsigned q = wsum[t];
        unsigned r = q;
#pragma unroll
        for (int off = 1; off < NW; off <<= 1) {
            unsigned n = __shfl_down_sync(0x0000FFFFu, r, off);
            if (t < NW - off) r += n;
        }
        wtail[t] = r - q;                  // sum of warp totals AFTER warp t
    }
    __syncthreads();
    unsigned beyond = (p - s) + wtail[wid];
#pragma unroll
    for (int j = 0; j < B; j++) {
        unsigned incl = loc[j] + beyond;                          // count(>=d)
        unsigned cnt  = loc[j] - ((j < B - 1) ? loc[j + 1] : 0u); // hist[d]
        unsigned gt   = incl - cnt;                               // count(>d)
        if (incl >= k && gt < k) { *sh_digit = (unsigned)(base + j); *sh_k = k - gt; }
    }
    __syncthreads();
}

__global__ __launch_bounds__(TPB, 4)
void topk_mask_kernel(const float* __restrict__ x, float* __restrict__ out) {
    __shared__ float    row[ROWLEN];       // 32 KB
    __shared__ unsigned hist[2048];        // 8 KB
    __shared__ unsigned wsum[NW];
    __shared__ unsigned wtail[NW];
    __shared__ unsigned sh_digit;
    __shared__ unsigned sh_k;

    const int t    = threadIdx.x;
    const int lane = t & 31;
    const int wid  = t >> 5;
    const size_t row_off = (size_t)blockIdx.x * ROWLEN;
    const float4* __restrict__ px   = reinterpret_cast<const float4*>(x + row_off);
    float4*       __restrict__ po   = reinterpret_cast<float4*>(out + row_off);
    float4*                    prow = reinterpret_cast<float4*>(row);

    // ---- zero histogram (2048 words, uint4 per thread) ----
    reinterpret_cast<uint4*>(hist)[t] = make_uint4(0u, 0u, 0u, 0u);
    __syncthreads();

    // ---- fused: global load -> smem stage + pass-1 histogram (11 bits) ----
#pragma unroll
    for (int i = 0; i < VPT; i++) {
        float4 a = px[t + i * TPB];
        prow[t + i * TPB] = a;
        atomicAdd(&hist[(__float_as_uint(a.x) & 0x7FFFFFFFu) >> 20], 1u);
        atomicAdd(&hist[(__float_as_uint(a.y) & 0x7FFFFFFFu) >> 20], 1u);
        atomicAdd(&hist[(__float_as_uint(a.z) & 0x7FFFFFFFu) >> 20], 1u);
        atomicAdd(&hist[(__float_as_uint(a.w) & 0x7FFFFFFFu) >> 20], 1u);
    }
    __syncthreads();

    unsigned k = KSEL;
    suffix_select<2048>(hist, k, t, lane, wid, wsum, wtail, &sh_digit, &sh_k);
    const unsigned d1 = sh_digit; k = sh_k;

    // ---- pass 2: digit = bits [9,20), among keys with top-11 == d1 ----
    reinterpret_cast<uint4*>(hist)[t] = make_uint4(0u, 0u, 0u, 0u);
    __syncthreads();
#pragma unroll
    for (int i = 0; i < VPT; i++) {
        float4 a = prow[t + i * TPB];
        const float* fa = reinterpret_cast<const float*>(&a);
#pragma unroll
        for (int c = 0; c < 4; c++) {
            unsigned key = __float_as_uint(fa[c]) & 0x7FFFFFFFu;
            if ((key >> 20) == d1)
                atomicAdd(&hist[(key >> 9) & 0x7FFu], 1u);
        }
    }
    __syncthreads();
    suffix_select<2048>(hist, k, t, lane, wid, wsum, wtail, &sh_digit, &sh_k);
    const unsigned d2 = sh_digit; k = sh_k;

    // ---- pass 3: digit = bits [0,9), among keys with top-22 == (d1,d2) ----
    const unsigned pref22 = (d1 << 11) | d2;   // == key >> 9 for candidates
    hist[t] = 0u;                               // only 512 bins needed
    __syncthreads();
#pragma unroll
    for (int i = 0; i < VPT; i++) {
        float4 a = prow[t + i * TPB];
        const float* fa = reinterpret_cast<const float*>(&a);
#pragma unroll
        for (int c = 0; c < 4; c++) {
            unsigned key = __float_as_uint(fa[c]) & 0x7FFFFFFFu;
            if ((key >> 9) == pref22)
                atomicAdd(&hist[key & 0x1FFu], 1u);
        }
    }
    __syncthreads();
    suffix_select<512>(hist, k, t, lane, wid, wsum, wtail, &sh_digit, &sh_k);

    const unsigned T = (pref22 << 9) | sh_digit;   // K-th largest |x| bit pattern

    // ---- epilogue: mask from smem, coalesced float4 store ----
#pragma unroll
    for (int i = 0; i < VPT; i++) {
        float4 o = prow[t + i * TPB];
        float* fo = reinterpret_cast<float*>(&o);
#pragma unroll
        for (int c = 0; c < 4; c++) {
            unsigned key = __float_as_uint(fo[c]) & 0x7FFFFFFFu;
            if (key < T) fo[c] = 0.0f;
        }
        po[t + i * TPB] = o;
    }
}

extern "C" void kernel_launch(void* const* d_in, const int* in_sizes, int n_in,
                              void* d_out, int out_size) {
    const float* x = (const float*)d_in[0];
    float* out = (float*)d_out;
    const int rows = in_sizes[0] / ROWLEN;   // 4096
    topk_mask_kernel<<<rows, TPB>>>(x, out);
}